// round 14
// baseline (speedup 1.0000x reference)
#include <cuda_runtime.h>
#include <math.h>

#define GN 256
#define NVOX (GN*GN*GN)          // 2^24
#define MAX_ID 32
#define NUM_CLASSES 13
#define NBINS ((MAX_ID+1)*NUM_CLASSES)   // 429
#define LUT_SZ (MAX_ID+3)                // 35
#define KEY_WALL  33
#define KEY_FLOOR 34
#define SURF_BIT  0x80

// ---------------- device scratch (no allocations allowed) ----------------
__device__ int           g_counts[NBINS];
__device__ int           g_sem_lut[LUT_SZ];
__device__ unsigned char g_labellut[256];  // key byte -> label | (key&0x80)
__device__ unsigned char g_key[NVOX];      // bit7=surface, low: 33=wall,34=floor,else inst
__device__ unsigned char g_lab[NVOX];      // bit7=surface, low 7: panoptic label

__device__ const float* g_geo;
__device__ const int*   g_inst;
__device__ const int*   g_sem;

// ---------------- kernel A: classify big buffers by content (3 warps) ----------------
__global__ void classifyK(const int* a, const int* b, const int* c) {
    __shared__ int smax[3];
    const int* bufs[3] = { a, b, c };
    int w = threadIdx.x >> 5, lane = threadIdx.x & 31;
    if (w < 3) {
        const int* p = bufs[w];
        int mx = -2147483647;
        for (int i = lane; i < 2048; i += 32) {
            int v = p[i * 769];
            mx = v > mx ? v : mx;
        }
        for (int o = 16; o > 0; o >>= 1) {
            int t = __shfl_xor_sync(0xFFFFFFFFu, mx, o);
            mx = t > mx ? t : mx;
        }
        if (lane == 0) smax[w] = mx;
    }
    __syncthreads();
    if (threadIdx.x == 0) {
        bool used[3] = { false, false, false };
        bool gs = false, ss = false, is = false;
        for (int t = 0; t < 3; t++)
            if (!used[t] && (smax[t] > 1000000 || smax[t] < 0)) {
                g_geo = (const float*)bufs[t]; used[t] = true; gs = true; break;
            }
        for (int t = 0; t < 3; t++)
            if (!used[t] && smax[t] < 13) {
                g_sem = bufs[t]; used[t] = true; ss = true; break;
            }
        for (int t = 0; t < 3; t++)
            if (!used[t]) { g_inst = bufs[t]; used[t] = true; is = true; break; }
        if (!gs) g_geo  = (const float*)a;
        if (!ss) g_sem  = c;
        if (!is) g_inst = b;
    }
    for (int i = threadIdx.x; i < NBINS; i += blockDim.x) g_counts[i] = 0;
}

// ---------------- kernel 1: joint histogram + key-grid (surface bit folded in) ----------------
__global__ void histK() {
    __shared__ int sc[NBINS];
    for (int i = threadIdx.x; i < NBINS; i += blockDim.x) sc[i] = 0;
    __syncthreads();

    const int4*   inst4 = (const int4*)g_inst;
    const int4*   sem4  = (const int4*)g_sem;
    const float4* geo4  = (const float4*)g_geo;
    uchar4*       key4  = (uchar4*)g_key;
    int stride = gridDim.x * blockDim.x;
    int n4 = NVOX / 4;
    for (int i = blockIdx.x * blockDim.x + threadIdx.x; i < n4; i += stride) {
        int4   v = __ldcs(&inst4[i]);
        int4   s = __ldcs(&sem4[i]);
        float4 g = __ldcs(&geo4[i]);
        unsigned ix;
        ix = (unsigned)(v.x * NUM_CLASSES + s.x); if (ix < NBINS) atomicAdd(&sc[ix], 1);
        ix = (unsigned)(v.y * NUM_CLASSES + s.y); if (ix < NBINS) atomicAdd(&sc[ix], 1);
        ix = (unsigned)(v.z * NUM_CLASSES + s.z); if (ix < NBINS) atomicAdd(&sc[ix], 1);
        ix = (unsigned)(v.w * NUM_CLASSES + s.w); if (ix < NBINS) atomicAdd(&sc[ix], 1);
        uchar4 k;
        k.x = ((s.x == 10) ? KEY_WALL : ((s.x == 11) ? KEY_FLOOR : (unsigned char)(v.x & 31)))
            | (fabsf(g.x) <= 1.5f ? SURF_BIT : 0);
        k.y = ((s.y == 10) ? KEY_WALL : ((s.y == 11) ? KEY_FLOOR : (unsigned char)(v.y & 31)))
            | (fabsf(g.y) <= 1.5f ? SURF_BIT : 0);
        k.z = ((s.z == 10) ? KEY_WALL : ((s.z == 11) ? KEY_FLOOR : (unsigned char)(v.z & 31)))
            | (fabsf(g.z) <= 1.5f ? SURF_BIT : 0);
        k.w = ((s.w == 10) ? KEY_WALL : ((s.w == 11) ? KEY_FLOOR : (unsigned char)(v.w & 31)))
            | (fabsf(g.w) <= 1.5f ? SURF_BIT : 0);
        key4[i] = k;
    }
    __syncthreads();
    for (int i = threadIdx.x; i < NBINS; i += blockDim.x)
        if (sc[i]) atomicAdd(&g_counts[i], sc[i]);
}

// ---------------- kernel 2: build LUTs (parallelized over ids) ----------------
__global__ void lutK(const int* __restrict__ ids2d, int n2d) {
    __shared__ int  sh_hist[MAX_ID + 1];
    __shared__ int  sh_sel[MAX_ID + 1];
    __shared__ int  sh_pano[MAX_ID + 1];
    __shared__ bool sh_in2d[MAX_ID + 1];
    __shared__ bool sh_pres[MAX_ID + 1];
    int t = threadIdx.x;

    if (t <= MAX_ID) {
        int h = 0, bestv = -2147483647, bi = 0;
        for (int c = 0; c < NUM_CLASSES; c++) {
            int cnt = g_counts[t * NUM_CLASSES + c];
            h += cnt;
            int v = (c == 0 || c == 10 || c == 11) ? -1 : cnt;
            if (v > bestv) { bestv = v; bi = c; }   // first max wins
        }
        sh_hist[t] = h;
        sh_sel[t]  = bi;
        bool in2 = false;
        for (int s = 0; s < n2d; s++) {
            int v = ids2d[s] + 1;
            if (v == t && t >= 1) in2 = true;
        }
        sh_in2d[t] = in2;
    }
    __syncthreads();

    if (t == 0) {
        int zp = 0;
        for (int i = 0; i <= MAX_ID; i++)
            if (sh_hist[i] > 0 && !sh_in2d[i]) zp = 1;
        int rank = 0;
        sh_pano[0] = 0;
        sh_pres[0] = false;
        for (int i = 1; i <= MAX_ID; i++) {
            bool p = sh_in2d[i] && (sh_hist[i] > 0);
            sh_pres[i] = p;
            if (p) rank++;
            sh_pano[i] = p ? (rank - 1 + zp + 2) : 0;
        }
        // sem_lut: zeros; [1]=wall; [2]=floor; then pano scatter (reference order)
        for (int k = 0; k < LUT_SZ; k++) g_sem_lut[k] = 0;
        g_sem_lut[1] = 10;
        g_sem_lut[2] = 11;
        for (int i = 1; i <= MAX_ID; i++) {
            int idx = sh_pano[i];
            int val = sh_pres[i] ? sh_sel[i] : 0;
            if (idx >= 0 && idx < LUT_SZ) g_sem_lut[idx] = val;
        }
    }
    __syncthreads();

    // key byte -> (panoptic label | surface bit preserved), 256 entries parallel
    for (int x = t; x < 256; x += blockDim.x) {
        int base = x & 0x7F;
        unsigned char val = 0;
        if (base < 32)             val = (unsigned char)sh_pano[base];
        else if (base == KEY_WALL)   val = 1;
        else if (base == KEY_FLOOR)  val = 2;
        g_labellut[x] = val | (unsigned char)(x & SURF_BIT);
    }
}

// ---------------- kernel 3: labelize keys -> label grid (16 B / thread) ----------------
__global__ void labelK() {
    __shared__ unsigned char lut[256];
    if (threadIdx.x < 256) lut[threadIdx.x] = g_labellut[threadIdx.x];
    __syncthreads();

    int t = blockIdx.x * blockDim.x + threadIdx.x;
    int n16 = NVOX / 16;
    if (t >= n16) return;
    uint4 in = __ldcs(&((const uint4*)g_key)[t]);
    unsigned w[4] = { in.x, in.y, in.z, in.w };
    uint4 outw;
    unsigned* po = (unsigned*)&outw;
    #pragma unroll
    for (int q = 0; q < 4; q++) {
        unsigned x = w[q];
        po[q] = (unsigned)lut[x & 0xFF]
              | ((unsigned)lut[(x >> 8) & 0xFF] << 8)
              | ((unsigned)lut[(x >> 16) & 0xFF] << 16)
              | ((unsigned)lut[(x >> 24) & 0xFF] << 24);
    }
    ((uint4*)g_lab)[t] = outw;
}

// ---------------- kernel 4: nn_search with word-window probe engine ----------------
__global__ void nnK(float* __restrict__ out, long long out_elems) {
    __shared__ float slut[LUT_SZ];
    if (threadIdx.x < LUT_SZ) slut[threadIdx.x] = (float)g_sem_lut[threadIdx.x];
    __syncthreads();

    int t = blockIdx.x * blockDim.x + threadIdx.x;   // 4 voxels per thread
    int n4 = NVOX / 4;
    if (t >= n4) return;
    int base = t * 4;

    uchar4 l4 = ((const uchar4*)g_lab)[t];
    int lab[4] = { l4.x & 0x7F, l4.y & 0x7F, l4.z & 0x7F, l4.w & 0x7F };
    unsigned pend = 0;
    if (lab[0] == 0 && (l4.x & SURF_BIT)) pend |= 1u;
    if (lab[1] == 0 && (l4.y & SURF_BIT)) pend |= 2u;
    if (lab[2] == 0 && (l4.z & SURF_BIT)) pend |= 4u;
    if (lab[3] == 0 && (l4.w & SURF_BIT)) pend |= 8u;

    if (pend) {
        int k0 = base & 255;
        int j0 = (base >> 8) & 255;
        int i0 = base >> 16;
        bool fast = ((unsigned)(i0 - 3) <= 250u) && ((unsigned)(j0 - 3) <= 250u)
                  && ((unsigned)(k0 - 4) <= 240u);
        if (fast) {
            // rows shared by all 4 voxels; 3 aligned word loads cover bytes [k0-4, k0+8)
            const unsigned char* bp = g_lab + (i0 << 16) + (j0 << 8) + k0 - 4;
            #pragma unroll 1
            for (int di = -3; di < 3 && pend; di++) {
                #pragma unroll 1
                for (int dj = -3; dj < 3 && pend; dj++) {
                    const unsigned char* rp = bp + di * 65536 + dj * 256;
                    unsigned w0 = *(const unsigned*)(rp);
                    unsigned w1 = *(const unsigned*)(rp + 4);
                    unsigned w2 = *(const unsigned*)(rp + 8);
                    unsigned long long lo = (unsigned long long)w0
                                          | ((unsigned long long)w1 << 32);
                    #pragma unroll
                    for (int q = 0; q < 4; q++) {
                        if (pend & (1u << q)) {
                            int sh = 8 * (q + 1);
                            unsigned long long win = (lo >> sh)
                                | ((unsigned long long)w2 << (64 - sh));
                            win &= 0x7F7F7F7F7F7FULL;                 // 6 bytes, surf bits off
                            unsigned long long m =
                                (win + 0x7F7F7F7F7F7FULL) & 0x808080808080ULL;
                            if (m) {
                                int b = (__ffsll((long long)m) - 1) >> 3;
                                lab[q] = (int)((win >> (8 * b)) & 0x7F);
                                pend &= ~(1u << q);
                            }
                        }
                    }
                }
            }
        } else {
            // slow path: torus wrap via masks, per pending voxel
            #pragma unroll
            for (int q = 0; q < 4; q++) {
                if (pend & (1u << q)) {
                    int k = k0 + q;
                    int label = 0;
                    #pragma unroll 1
                    for (int di = -3; di < 3 && !label; di++) {
                        int ii = (i0 + di) & 255;
                        #pragma unroll 1
                        for (int dj = -3; dj < 3; dj++) {
                            int jj = (j0 + dj) & 255;
                            const unsigned char* row = &g_lab[(ii << 16) | (jj << 8)];
                            int v = 0;
                            #pragma unroll
                            for (int dk = -3; dk < 3; dk++) {
                                int w = row[(k + dk) & 255] & 0x7F;
                                if (!v && w) v = w;
                            }
                            if (v) { label = v; break; }
                        }
                    }
                    lab[q] = label;
                }
            }
        }
    }

    float4 po = make_float4((float)lab[0], (float)lab[1], (float)lab[2], (float)lab[3]);
    float4 so = make_float4(slut[lab[0]], slut[lab[1]], slut[lab[2]], slut[lab[3]]);

    if ((long long)base + 3 < out_elems)
        __stcs(&((float4*)out)[t], po);
    if ((long long)base + NVOX + 3 < out_elems)
        __stcs(&((float4*)(out + NVOX))[t], so);
}

// ---------------- launch ----------------
extern "C" void kernel_launch(void* const* d_in, const int* in_sizes, int n_in,
                              void* d_out, int out_size) {
    const int* big[3] = { 0, 0, 0 };
    const int* ids2d = 0;
    int n2d = 0, nb = 0;
    for (int t = 0; t < n_in; t++) {
        if (in_sizes[t] < 1024) { ids2d = (const int*)d_in[t]; n2d = in_sizes[t]; }
        else if (nb < 3)        { big[nb++] = (const int*)d_in[t]; }
    }

    float* out = (float*)d_out;
    long long out_elems = (long long)out_size;

    classifyK<<<1, 128>>>(big[0], big[1], big[2]);
    histK<<<2048, 256>>>();
    if (ids2d) lutK<<<1, 64>>>(ids2d, n2d);
    labelK<<<(NVOX / 16 + 255) / 256, 256>>>();
    nnK<<<(NVOX / 4 + 255) / 256, 256>>>(out, out_elems);
}

// round 15
// speedup vs baseline: 1.3365x; 1.3365x over previous
#include <cuda_runtime.h>
#include <math.h>

#define GN 256
#define NVOX (GN*GN*GN)          // 2^24
#define MAX_ID 32
#define NUM_CLASSES 13
#define NBINS ((MAX_ID+1)*NUM_CLASSES)   // 429
#define LUT_SZ (MAX_ID+3)                // 35
#define SURF_BIT 0x80

// ---------------- device scratch (no allocations allowed) ----------------
__device__ int           g_counts[NBINS];
__device__ int           g_pano_lut[MAX_ID+1];
__device__ int           g_sem_lut[LUT_SZ];
__device__ unsigned char g_lab[NVOX];   // bit7 = surface, low7 = panoptic label

__device__ const float* g_geo;
__device__ const int*   g_inst;
__device__ const int*   g_sem;

// ---------------- kernel A: classify big buffers by content (3 warps) ----------------
__global__ void classifyK(const int* a, const int* b, const int* c) {
    __shared__ int smax[3];
    const int* bufs[3] = { a, b, c };
    int w = threadIdx.x >> 5, lane = threadIdx.x & 31;
    if (w < 3) {
        const int* p = bufs[w];
        int mx = -2147483647;
        for (int i = lane; i < 2048; i += 32) {
            int v = p[i * 769];
            mx = v > mx ? v : mx;
        }
        for (int o = 16; o > 0; o >>= 1) {
            int t = __shfl_xor_sync(0xFFFFFFFFu, mx, o);
            mx = t > mx ? t : mx;
        }
        if (lane == 0) smax[w] = mx;
    }
    __syncthreads();
    if (threadIdx.x == 0) {
        bool used[3] = { false, false, false };
        bool gs = false, ss = false, is = false;
        for (int t = 0; t < 3; t++)
            if (!used[t] && (smax[t] > 1000000 || smax[t] < 0)) {
                g_geo = (const float*)bufs[t]; used[t] = true; gs = true; break;
            }
        for (int t = 0; t < 3; t++)
            if (!used[t] && smax[t] < 13) {
                g_sem = bufs[t]; used[t] = true; ss = true; break;
            }
        for (int t = 0; t < 3; t++)
            if (!used[t]) { g_inst = bufs[t]; used[t] = true; is = true; break; }
        if (!gs) g_geo  = (const float*)a;
        if (!ss) g_sem  = c;
        if (!is) g_inst = b;
    }
    for (int i = threadIdx.x; i < NBINS; i += blockDim.x) g_counts[i] = 0;
}

// ---------------- kernel 1: joint (instance, semantic) histogram (R10 form) ----------------
__global__ void histK() {
    __shared__ int sc[NBINS];
    for (int i = threadIdx.x; i < NBINS; i += blockDim.x) sc[i] = 0;
    __syncthreads();

    const int4* inst4 = (const int4*)g_inst;
    const int4* sem4  = (const int4*)g_sem;
    int stride = gridDim.x * blockDim.x;
    int n4 = NVOX / 4;
    for (int i = blockIdx.x * blockDim.x + threadIdx.x; i < n4; i += stride) {
        int4 v = inst4[i];
        int4 s = sem4[i];
        unsigned ix;
        ix = (unsigned)(v.x * NUM_CLASSES + s.x); if (ix < NBINS) atomicAdd(&sc[ix], 1);
        ix = (unsigned)(v.y * NUM_CLASSES + s.y); if (ix < NBINS) atomicAdd(&sc[ix], 1);
        ix = (unsigned)(v.z * NUM_CLASSES + s.z); if (ix < NBINS) atomicAdd(&sc[ix], 1);
        ix = (unsigned)(v.w * NUM_CLASSES + s.w); if (ix < NBINS) atomicAdd(&sc[ix], 1);
    }
    __syncthreads();
    for (int i = threadIdx.x; i < NBINS; i += blockDim.x)
        if (sc[i]) atomicAdd(&g_counts[i], sc[i]);
}

// ---------------- kernel 2: build LUTs (parallelized over ids) ----------------
__global__ void lutK(const int* __restrict__ ids2d, int n2d) {
    __shared__ int  sh_hist[MAX_ID + 1];
    __shared__ int  sh_sel[MAX_ID + 1];
    __shared__ int  sh_pano[MAX_ID + 1];
    __shared__ bool sh_in2d[MAX_ID + 1];
    __shared__ bool sh_pres[MAX_ID + 1];
    int t = threadIdx.x;

    if (t <= MAX_ID) {
        int h = 0, bestv = -2147483647, bi = 0;
        for (int c = 0; c < NUM_CLASSES; c++) {
            int cnt = g_counts[t * NUM_CLASSES + c];
            h += cnt;
            int v = (c == 0 || c == 10 || c == 11) ? -1 : cnt;
            if (v > bestv) { bestv = v; bi = c; }   // first max wins
        }
        sh_hist[t] = h;
        sh_sel[t]  = bi;
        bool in2 = false;
        for (int s = 0; s < n2d; s++) {
            int v = ids2d[s] + 1;
            if (v == t && t >= 1) in2 = true;
        }
        sh_in2d[t] = in2;
    }
    __syncthreads();

    if (t == 0) {
        int zp = 0;
        for (int i = 0; i <= MAX_ID; i++)
            if (sh_hist[i] > 0 && !sh_in2d[i]) zp = 1;
        int rank = 0;
        sh_pano[0] = 0;
        sh_pres[0] = false;
        g_pano_lut[0] = 0;
        for (int i = 1; i <= MAX_ID; i++) {
            bool p = sh_in2d[i] && (sh_hist[i] > 0);
            sh_pres[i] = p;
            if (p) rank++;
            sh_pano[i] = p ? (rank - 1 + zp + 2) : 0;
            g_pano_lut[i] = sh_pano[i];
        }
        // sem_lut: zeros; [1]=wall; [2]=floor; then pano scatter (reference order)
        for (int k = 0; k < LUT_SZ; k++) g_sem_lut[k] = 0;
        g_sem_lut[1] = 10;
        g_sem_lut[2] = 11;
        for (int i = 1; i <= MAX_ID; i++) {
            int idx = sh_pano[i];
            int val = sh_pres[i] ? sh_sel[i] : 0;
            if (idx >= 0 && idx < LUT_SZ) g_sem_lut[idx] = val;
        }
    }
}

// ---------------- kernel 3: label grid with surface bit (reads inst/sem from L2 + geo) ----------------
__global__ void grid0K() {
    __shared__ unsigned char lut[MAX_ID + 1];
    if (threadIdx.x <= MAX_ID) lut[threadIdx.x] = (unsigned char)g_pano_lut[threadIdx.x];
    __syncthreads();

    int i = blockIdx.x * blockDim.x + threadIdx.x;
    int n4 = NVOX / 4;
    if (i >= n4) return;
    int4   v = ((const int4*)g_inst)[i];
    int4   s = ((const int4*)g_sem)[i];
    float4 g = ((const float4*)g_geo)[i];
    v.x &= 31; v.y &= 31; v.z &= 31; v.w &= 31;
    uchar4 o;
    o.x = ((s.x == 10) ? 1 : ((s.x == 11) ? 2 : lut[v.x])) | (fabsf(g.x) <= 1.5f ? SURF_BIT : 0);
    o.y = ((s.y == 10) ? 1 : ((s.y == 11) ? 2 : lut[v.y])) | (fabsf(g.y) <= 1.5f ? SURF_BIT : 0);
    o.z = ((s.z == 10) ? 1 : ((s.z == 11) ? 2 : lut[v.z])) | (fabsf(g.z) <= 1.5f ? SURF_BIT : 0);
    o.w = ((s.w == 10) ? 1 : ((s.w == 11) ? 2 : lut[v.w])) | (fabsf(g.w) <= 1.5f ? SURF_BIT : 0);
    ((uchar4*)g_lab)[i] = o;
}

// ---------------- kernel 4: nn_search (R10-style byte probes) + float4 outputs ----------------
__global__ void nnK(float* __restrict__ out, long long out_elems) {
    __shared__ float slut[LUT_SZ];
    if (threadIdx.x < LUT_SZ) slut[threadIdx.x] = (float)g_sem_lut[threadIdx.x];
    __syncthreads();

    int t = blockIdx.x * blockDim.x + threadIdx.x;   // 4 voxels per thread
    int n4 = NVOX / 4;
    if (t >= n4) return;
    int base = t * 4;

    uchar4 l4 = ((const uchar4*)g_lab)[t];
    int raw[4] = { l4.x, l4.y, l4.z, l4.w };
    int lab[4];

    #pragma unroll
    for (int q = 0; q < 4; q++) {
        int val = raw[q];
        int label = val & 0x7F;
        if (label == 0 && (val & SURF_BIT)) {
            int idx = base + q;
            int k = idx & 255;
            int j = (idx >> 8) & 255;
            int i = idx >> 16;
            // lexicographic offsets di,dj,dk in [-3,3); first positive neighbor wins
            #pragma unroll 1
            for (int di = -3; di < 3 && !label; di++) {
                int ii = (i + di) & 255;
                #pragma unroll 1
                for (int dj = -3; dj < 3 && !label; dj++) {
                    int jj = (j + dj) & 255;
                    const unsigned char* row = &g_lab[(ii << 16) | (jj << 8)];
                    #pragma unroll
                    for (int dk = -3; dk < 3; dk++) {
                        int v = row[(k + dk) & 255] & 0x7F;
                        if (v > 0) { label = v; break; }
                    }
                }
            }
        }
        lab[q] = label;
    }

    float4 po = make_float4((float)lab[0], (float)lab[1], (float)lab[2], (float)lab[3]);
    float4 so = make_float4(slut[lab[0]], slut[lab[1]], slut[lab[2]], slut[lab[3]]);

    if ((long long)base + 3 < out_elems)
        ((float4*)out)[t] = po;
    if ((long long)base + NVOX + 3 < out_elems)
        ((float4*)(out + NVOX))[t] = so;
}

// ---------------- launch ----------------
extern "C" void kernel_launch(void* const* d_in, const int* in_sizes, int n_in,
                              void* d_out, int out_size) {
    const int* big[3] = { 0, 0, 0 };
    const int* ids2d = 0;
    int n2d = 0, nb = 0;
    for (int t = 0; t < n_in; t++) {
        if (in_sizes[t] < 1024) { ids2d = (const int*)d_in[t]; n2d = in_sizes[t]; }
        else if (nb < 3)        { big[nb++] = (const int*)d_in[t]; }
    }

    float* out = (float*)d_out;
    long long out_elems = (long long)out_size;

    classifyK<<<1, 128>>>(big[0], big[1], big[2]);
    histK<<<1024, 256>>>();
    if (ids2d) lutK<<<1, 64>>>(ids2d, n2d);
    grid0K<<<(NVOX / 4 + 255) / 256, 256>>>();
    nnK<<<(NVOX / 4 + 255) / 256, 256>>>(out, out_elems);
}

// round 16
// speedup vs baseline: 1.3761x; 1.0296x over previous
#include <cuda_runtime.h>
#include <math.h>

#define GN 256
#define NVOX (GN*GN*GN)          // 2^24
#define MAX_ID 32
#define NUM_CLASSES 13
#define NBINS ((MAX_ID+1)*NUM_CLASSES)   // 429
#define LUT_SZ (MAX_ID+3)                // 35
#define KEY_WALL  33
#define KEY_FLOOR 34
#define SURF_BIT  0x80
#define NCOPY 16

// ---------------- device scratch (no allocations allowed) ----------------
__device__ int           g_counts[NBINS];
__device__ int           g_sem_lut[LUT_SZ];
__device__ unsigned char g_labellut[256];  // key byte -> label | (key&0x80)
__device__ unsigned char g_key[NVOX];      // bit7=surface, low: 33=wall,34=floor,else inst
__device__ unsigned char g_lab[NVOX];      // bit7=surface, low7: panoptic label
__device__ unsigned char g_W[NVOX];        // first positive label in row window [k-3,k+2]

__device__ const float* g_geo;
__device__ const int*   g_inst;
__device__ const int*   g_sem;

// ---------------- kernel A: classify big buffers by content (3 warps) ----------------
__global__ void classifyK(const int* a, const int* b, const int* c) {
    __shared__ int smax[3];
    const int* bufs[3] = { a, b, c };
    int w = threadIdx.x >> 5, lane = threadIdx.x & 31;
    if (w < 3) {
        const int* p = bufs[w];
        int mx = -2147483647;
        for (int i = lane; i < 2048; i += 32) {
            int v = p[i * 769];
            mx = v > mx ? v : mx;
        }
        for (int o = 16; o > 0; o >>= 1) {
            int t = __shfl_xor_sync(0xFFFFFFFFu, mx, o);
            mx = t > mx ? t : mx;
        }
        if (lane == 0) smax[w] = mx;
    }
    __syncthreads();
    if (threadIdx.x == 0) {
        bool used[3] = { false, false, false };
        bool gs = false, ss = false, is = false;
        for (int t = 0; t < 3; t++)
            if (!used[t] && (smax[t] > 1000000 || smax[t] < 0)) {
                g_geo = (const float*)bufs[t]; used[t] = true; gs = true; break;
            }
        for (int t = 0; t < 3; t++)
            if (!used[t] && smax[t] < 13) {
                g_sem = bufs[t]; used[t] = true; ss = true; break;
            }
        for (int t = 0; t < 3; t++)
            if (!used[t]) { g_inst = bufs[t]; used[t] = true; is = true; break; }
        if (!gs) g_geo  = (const float*)a;
        if (!ss) g_sem  = c;
        if (!is) g_inst = b;
    }
    for (int i = threadIdx.x; i < NBINS; i += blockDim.x) g_counts[i] = 0;
}

// ---------------- kernel 1: joint histogram (lane-private copies) + key grid ----------------
__global__ void histK() {
    __shared__ int sc[NBINS * NCOPY];   // ~27.4 KB
    for (int i = threadIdx.x; i < NBINS * NCOPY; i += blockDim.x) sc[i] = 0;
    __syncthreads();

    const int4*   inst4 = (const int4*)g_inst;
    const int4*   sem4  = (const int4*)g_sem;
    const float4* geo4  = (const float4*)g_geo;
    uchar4*       key4  = (uchar4*)g_key;
    int copy = threadIdx.x & (NCOPY - 1);
    int stride = gridDim.x * blockDim.x;
    int n4 = NVOX / 4;
    for (int i = blockIdx.x * blockDim.x + threadIdx.x; i < n4; i += stride) {
        int4   v = inst4[i];
        int4   s = sem4[i];
        float4 g = geo4[i];
        unsigned ix;
        ix = (unsigned)(v.x * NUM_CLASSES + s.x); if (ix < NBINS) atomicAdd(&sc[ix * NCOPY + copy], 1);
        ix = (unsigned)(v.y * NUM_CLASSES + s.y); if (ix < NBINS) atomicAdd(&sc[ix * NCOPY + copy], 1);
        ix = (unsigned)(v.z * NUM_CLASSES + s.z); if (ix < NBINS) atomicAdd(&sc[ix * NCOPY + copy], 1);
        ix = (unsigned)(v.w * NUM_CLASSES + s.w); if (ix < NBINS) atomicAdd(&sc[ix * NCOPY + copy], 1);
        uchar4 k;
        k.x = ((s.x == 10) ? KEY_WALL : ((s.x == 11) ? KEY_FLOOR : (unsigned char)(v.x & 31)))
            | (fabsf(g.x) <= 1.5f ? SURF_BIT : 0);
        k.y = ((s.y == 10) ? KEY_WALL : ((s.y == 11) ? KEY_FLOOR : (unsigned char)(v.y & 31)))
            | (fabsf(g.y) <= 1.5f ? SURF_BIT : 0);
        k.z = ((s.z == 10) ? KEY_WALL : ((s.z == 11) ? KEY_FLOOR : (unsigned char)(v.z & 31)))
            | (fabsf(g.z) <= 1.5f ? SURF_BIT : 0);
        k.w = ((s.w == 10) ? KEY_WALL : ((s.w == 11) ? KEY_FLOOR : (unsigned char)(v.w & 31)))
            | (fabsf(g.w) <= 1.5f ? SURF_BIT : 0);
        key4[i] = k;
    }
    __syncthreads();
    for (int bin = threadIdx.x; bin < NBINS; bin += blockDim.x) {
        int s = 0;
        #pragma unroll
        for (int c = 0; c < NCOPY; c++) s += sc[bin * NCOPY + c];
        if (s) atomicAdd(&g_counts[bin], s);
    }
}

// ---------------- kernel 2: build LUTs (parallelized over ids) ----------------
__global__ void lutK(const int* __restrict__ ids2d, int n2d) {
    __shared__ int  sh_hist[MAX_ID + 1];
    __shared__ int  sh_sel[MAX_ID + 1];
    __shared__ int  sh_pano[MAX_ID + 1];
    __shared__ bool sh_in2d[MAX_ID + 1];
    __shared__ bool sh_pres[MAX_ID + 1];
    int t = threadIdx.x;

    if (t <= MAX_ID) {
        int h = 0, bestv = -2147483647, bi = 0;
        for (int c = 0; c < NUM_CLASSES; c++) {
            int cnt = g_counts[t * NUM_CLASSES + c];
            h += cnt;
            int v = (c == 0 || c == 10 || c == 11) ? -1 : cnt;
            if (v > bestv) { bestv = v; bi = c; }   // first max wins
        }
        sh_hist[t] = h;
        sh_sel[t]  = bi;
        bool in2 = false;
        for (int s = 0; s < n2d; s++) {
            int v = ids2d[s] + 1;
            if (v == t && t >= 1) in2 = true;
        }
        sh_in2d[t] = in2;
    }
    __syncthreads();

    if (t == 0) {
        int zp = 0;
        for (int i = 0; i <= MAX_ID; i++)
            if (sh_hist[i] > 0 && !sh_in2d[i]) zp = 1;
        int rank = 0;
        sh_pano[0] = 0;
        sh_pres[0] = false;
        for (int i = 1; i <= MAX_ID; i++) {
            bool p = sh_in2d[i] && (sh_hist[i] > 0);
            sh_pres[i] = p;
            if (p) rank++;
            sh_pano[i] = p ? (rank - 1 + zp + 2) : 0;
        }
        for (int k = 0; k < LUT_SZ; k++) g_sem_lut[k] = 0;
        g_sem_lut[1] = 10;
        g_sem_lut[2] = 11;
        for (int i = 1; i <= MAX_ID; i++) {
            int idx = sh_pano[i];
            int val = sh_pres[i] ? sh_sel[i] : 0;
            if (idx >= 0 && idx < LUT_SZ) g_sem_lut[idx] = val;
        }
    }
    __syncthreads();

    for (int x = t; x < 256; x += blockDim.x) {
        int base = x & 0x7F;
        unsigned char val = 0;
        if (base < 32)             val = (unsigned char)sh_pano[base];
        else if (base == KEY_WALL)   val = 1;
        else if (base == KEY_FLOOR)  val = 2;
        g_labellut[x] = val | (unsigned char)(x & SURF_BIT);
    }
}

// ---------------- kernel 3: labelize + row-window W grid (16 B / thread) ----------------
// Thread layout: 16 consecutive lanes own one 256-byte row (lane&15 = segment).
__global__ void labelK() {
    __shared__ unsigned char lut[256];
    if (threadIdx.x < 256) lut[threadIdx.x] = g_labellut[threadIdx.x];
    __syncthreads();

    int t = blockIdx.x * blockDim.x + threadIdx.x;   // 1M threads, 16 bytes each
    int lane = threadIdx.x & 31;

    uint4 kin = ((const uint4*)g_key)[t];

    // map 16 key bytes -> label bytes (with surf) and plain labels (no surf)
    unsigned long long lb_lo = 0, lb_hi = 0, pl_lo = 0, pl_hi = 0;
    unsigned kw[4] = { kin.x, kin.y, kin.z, kin.w };
    #pragma unroll
    for (int wd = 0; wd < 4; wd++) {
        #pragma unroll
        for (int n = 0; n < 4; n++) {
            unsigned x = (kw[wd] >> (8 * n)) & 0xFF;
            unsigned long long c = lut[x];
            int bytep = wd * 4 + n;
            if (bytep < 8) { lb_lo |= c << (8 * bytep); pl_lo |= (c & 0x7F) << (8 * bytep); }
            else           { lb_hi |= c << (8 * (bytep - 8)); pl_hi |= (c & 0x7F) << (8 * (bytep - 8)); }
        }
    }

    // halo exchange within the row (torus wrap along k)
    int prevLane = (lane & 16) | ((lane - 1) & 15);
    int nextLane = (lane & 16) | ((lane + 1) & 15);
    unsigned prev3 = __shfl_sync(0xFFFFFFFFu, (unsigned)(pl_hi >> 40), prevLane); // bytes 13,14,15
    unsigned next2 = __shfl_sync(0xFFFFFFFFu, (unsigned)(pl_lo & 0xFFFF), nextLane); // bytes 0,1

    // extended byte stream e[0..20] = prev3 | own16 | next2 packed into 3 u64
    unsigned long long e0 = (unsigned long long)prev3 | (pl_lo << 24);               // e0..e7
    unsigned long long e1 = (pl_lo >> 40) | (pl_hi << 24);                            // e8..e15
    unsigned long long e2 = (pl_hi >> 40) | ((unsigned long long)next2 << 24);        // e16..e20

    // W[b] = first nonzero byte of e[b..b+5]  (window [k-3, k+2] for own byte b)
    unsigned long long w_lo = 0, w_hi = 0;
    #pragma unroll
    for (int b = 0; b < 16; b++) {
        unsigned long long win;
        if (b == 0)      win = e0;
        else if (b < 8)  win = (e0 >> (8 * b)) | (e1 << (64 - 8 * b));
        else if (b == 8) win = e1;
        else             win = (e1 >> (8 * (b - 8))) | (e2 << (64 - 8 * (b - 8)));
        win &= 0xFFFFFFFFFFFFULL;   // 6 bytes
        unsigned long long m = (win + 0x7F7F7F7F7F7FULL) & 0x808080808080ULL;
        unsigned long long lbl = 0;
        if (m) {
            int sh = (__ffsll((long long)m) - 1) & ~7;
            lbl = (win >> sh) & 0x7F;
        }
        if (b < 8) w_lo |= lbl << (8 * b);
        else       w_hi |= lbl << (8 * (b - 8));
    }

    uint4 lout, wout;
    lout.x = (unsigned)lb_lo; lout.y = (unsigned)(lb_lo >> 32);
    lout.z = (unsigned)lb_hi; lout.w = (unsigned)(lb_hi >> 32);
    wout.x = (unsigned)w_lo;  wout.y = (unsigned)(w_lo >> 32);
    wout.z = (unsigned)w_hi;  wout.w = (unsigned)(w_hi >> 32);
    ((uint4*)g_lab)[t] = lout;
    ((uint4*)g_W)[t]   = wout;
}

// ---------------- kernel 4: nn_search via W probes + float4 outputs ----------------
__global__ void nnK(float* __restrict__ out, long long out_elems) {
    __shared__ float slut[LUT_SZ];
    if (threadIdx.x < LUT_SZ) slut[threadIdx.x] = (float)g_sem_lut[threadIdx.x];
    __syncthreads();

    int t = blockIdx.x * blockDim.x + threadIdx.x;   // 4 voxels per thread
    int n4 = NVOX / 4;
    if (t >= n4) return;
    int base = t * 4;

    uchar4 l4 = ((const uchar4*)g_lab)[t];
    int raw[4] = { l4.x, l4.y, l4.z, l4.w };
    int lab[4];

    int j0 = (base >> 8) & 255;
    int i0 = base >> 16;

    #pragma unroll
    for (int q = 0; q < 4; q++) {
        int val = raw[q];
        int label = val & 0x7F;
        if (label == 0 && (val & SURF_BIT)) {
            int k = (base + q) & 255;
            // one W probe per (di,dj): W holds first positive of that row's k-window
            #pragma unroll 1
            for (int di = -3; di < 3 && !label; di++) {
                int ii = (i0 + di) & 255;
                #pragma unroll 1
                for (int dj = -3; dj < 3; dj++) {
                    int jj = (j0 + dj) & 255;
                    int w = g_W[(ii << 16) | (jj << 8) | k];
                    if (w) { label = w; break; }
                }
            }
        }
        lab[q] = label;
    }

    float4 po = make_float4((float)lab[0], (float)lab[1], (float)lab[2], (float)lab[3]);
    float4 so = make_float4(slut[lab[0]], slut[lab[1]], slut[lab[2]], slut[lab[3]]);

    if ((long long)base + 3 < out_elems)
        ((float4*)out)[t] = po;
    if ((long long)base + NVOX + 3 < out_elems)
        ((float4*)(out + NVOX))[t] = so;
}

// ---------------- launch ----------------
extern "C" void kernel_launch(void* const* d_in, const int* in_sizes, int n_in,
                              void* d_out, int out_size) {
    const int* big[3] = { 0, 0, 0 };
    const int* ids2d = 0;
    int n2d = 0, nb = 0;
    for (int t = 0; t < n_in; t++) {
        if (in_sizes[t] < 1024) { ids2d = (const int*)d_in[t]; n2d = in_sizes[t]; }
        else if (nb < 3)        { big[nb++] = (const int*)d_in[t]; }
    }

    float* out = (float*)d_out;
    long long out_elems = (long long)out_size;

    classifyK<<<1, 128>>>(big[0], big[1], big[2]);
    histK<<<2048, 256>>>();
    if (ids2d) lutK<<<1, 64>>>(ids2d, n2d);
    labelK<<<NVOX / 16 / 256, 256>>>();
    nnK<<<NVOX / 4 / 256, 256>>>(out, out_elems);
}